// round 1
// baseline (speedup 1.0000x reference)
#include <cuda_runtime.h>

#define B 16
#define A 3
#define C 80
#define H 76
#define W 76
#define T 50
#define HW (H*W)                 // 5776
#define CNT (B*A*H*W)            // 277248
#define CH (5+C)                 // 85
#define INCH (A*CH)              // 255

// Accumulators: 0 sx, 1 sy, 2 sw, 3 sh, 4 sconf_obj, 5 scls, 6 n_m, 7 sconf_noobj, 8 n_nm
__device__ float g_acc[9];
__device__ unsigned char g_objhit[CNT];

__device__ __forceinline__ float sigm(float z) { return 1.f / (1.f + expf(-z)); }

// Mirrors reference: -(t*clip(log p,-100) + (1-t)*clip(log(1-p),-100))
__device__ __forceinline__ float bce_f(float p, float t) {
    float lp = fmaxf(logf(p), -100.f);
    float lq = fmaxf(logf(1.f - p), -100.f);
    return -(t * lp + (1.f - t) * lq);
}

__global__ void k_init() {
    int i = blockIdx.x * blockDim.x + threadIdx.x;
    if (i < CNT) g_objhit[i] = 0;
    if (blockIdx.x == 0 && threadIdx.x < 9) g_acc[threadIdx.x] = 0.f;
}

// One block, B*T = 800 threads. Phase A: per-target geometry + objhit scatter
// + publish (cell, cls) to smem. Phase B: winner resolution (last target wins)
// + multi-hot class set + masked-cell loss terms via direct gather.
__global__ void k_targets(const float* __restrict__ inp, const float* __restrict__ tgt) {
    __shared__ int s_cell[B * T];
    __shared__ int s_cls[B * T];
    const float aw[3] = {1.25f, 2.0f, 4.125f};   // ANCHORS / (608/76)
    const float ah[3] = {1.625f, 3.75f, 2.875f};

    int tid = threadIdx.x;            // 0..799
    int b = tid / T, tt = tid - b * T;
    const float* tp = tgt + (size_t)(b * T + tt) * 5;
    float c0 = tp[0], c1 = tp[1], c2 = tp[2], c3 = tp[3], c4 = tp[4];
    bool valid = (c0 + c1 + c2 + c3 + c4) != 0.f;
    int cls = (int)c0;
    float gx = c1 * (float)W, gy = c2 * (float)H;
    float gw = c3 * (float)W, gh = c4 * (float)H;
    int gi = (int)gx, gj = (int)gy;
    bool ok = valid && (gj < H) && (gi < W);

    float a1 = (gw + 1.f) * (gh + 1.f);
    float bestv = -1.f; int best = 0;
    #pragma unroll
    for (int a = 0; a < 3; a++) {
        float inter = fmaxf(fminf(gw, aw[a]) + 1.f, 0.f) * fmaxf(fminf(gh, ah[a]) + 1.f, 0.f);
        float a2 = (aw[a] + 1.f) * (ah[a] + 1.f);
        float iou = inter / (a1 + a2 - inter + 1e-16f);
        if (iou > bestv) { bestv = iou; best = a; }
        if (valid && iou > 0.5f && gj >= 0 && gj < H && gi >= 0 && gi < W) {
            g_objhit[((b * A + a) * H + gj) * W + gi] = 1;  // same value from all writers: no race issue
        }
    }
    int cell = ok ? ((b * A + best) * H + gj) * W + gi : -1;
    s_cell[tid] = cell;
    s_cls[tid] = cls;
    __syncthreads();

    if (cell < 0) return;

    // Winner: last (largest tt) among same-batch targets mapping to same cell.
    // tcls is multi-hot: every ok target hitting this cell sets its class bit.
    unsigned cm0 = 0, cm1 = 0, cm2 = 0;
    bool win = true;
    int base = b * T;
    for (int u = 0; u < T; u++) {
        if (s_cell[base + u] == cell) {
            if (u > tt) win = false;
            int cc = s_cls[base + u];
            if (cc < 32)       cm0 |= 1u << cc;
            else if (cc < 64)  cm1 |= 1u << (cc - 32);
            else               cm2 |= 1u << (cc - 64);
        }
    }
    if (!win) return;

    float tx = gx - (float)gi;
    float ty = gy - (float)gj;
    float tw = logf(gw / aw[best] + 1e-16f);
    float th = logf(gh / ah[best] + 1e-16f);

    const float* p = inp + (size_t)(b * INCH + best * CH) * HW + gj * W + gi;
    float bx = bce_f(sigm(p[0]), tx);
    float by = bce_f(sigm(p[HW]), ty);
    float dw = p[2 * HW] - tw; dw *= dw;
    float dh = p[3 * HW] - th; dh *= dh;
    float bconf = -fmaxf(logf(sigm(p[4 * HW])), -100.f);  // bce(conf, 1)
    float scls = 0.f;
    #pragma unroll 4
    for (int c = 0; c < C; c++) {
        unsigned bit = (c < 32) ? (cm0 >> c) : (c < 64) ? (cm1 >> (c - 32)) : (cm2 >> (c - 64));
        float t = (bit & 1u) ? 1.f : 0.f;
        scls += bce_f(sigm(p[(size_t)(5 + c) * HW]), t);
    }
    atomicAdd(&g_acc[0], bx);
    atomicAdd(&g_acc[1], by);
    atomicAdd(&g_acc[2], dw);
    atomicAdd(&g_acc[3], dh);
    atomicAdd(&g_acc[4], bconf);
    atomicAdd(&g_acc[5], scls);
    atomicAdd(&g_acc[6], 1.f);
}

// Dense pass over the conf plane only: no-object BCE + n_nm.
__global__ void k_conf(const float* __restrict__ inp) {
    int i = blockIdx.x * blockDim.x + threadIdx.x;
    float v = 0.f, n = 0.f;
    if (i < CNT) {
        if (!g_objhit[i]) {
            int b = i / (A * HW);
            int r = i - b * (A * HW);
            int a = r / HW;
            int hw = r - a * HW;
            float z = inp[(size_t)(b * INCH + a * CH + 4) * HW + hw];
            float s = sigm(z);
            v = -fmaxf(logf(1.f - s), -100.f);   // bce(conf, 0)
            n = 1.f;
        }
    }
    // warp reduce
    #pragma unroll
    for (int o = 16; o > 0; o >>= 1) {
        v += __shfl_down_sync(0xffffffffu, v, o);
        n += __shfl_down_sync(0xffffffffu, n, o);
    }
    __shared__ float sv[8], sn[8];
    int wid = threadIdx.x >> 5, lid = threadIdx.x & 31;
    if (lid == 0) { sv[wid] = v; sn[wid] = n; }
    __syncthreads();
    if (wid == 0) {
        int nw = blockDim.x >> 5;
        v = (lid < nw) ? sv[lid] : 0.f;
        n = (lid < nw) ? sn[lid] : 0.f;
        #pragma unroll
        for (int o = 4; o > 0; o >>= 1) {
            v += __shfl_down_sync(0xffffffffu, v, o);
            n += __shfl_down_sync(0xffffffffu, n, o);
        }
        if (lid == 0) {
            atomicAdd(&g_acc[7], v);
            atomicAdd(&g_acc[8], n);
        }
    }
}

__global__ void k_final(float* __restrict__ out) {
    const float inv = 1.f / (float)CNT;
    float nm  = g_acc[6];
    float nnm = g_acc[8];
    float lx = (g_acc[0] * inv) / nm;
    float ly = (g_acc[1] * inv) / nm;
    float lw = (g_acc[2] * inv) / nm;
    float lh = (g_acc[3] * inv) / nm;
    float lc = (g_acc[4] * inv) / nm + 0.5f * (g_acc[7] * inv) / nnm;
    float lcls = g_acc[5] / (nm * (float)C) / nm;
    float loss = 2.5f * (lx + ly) + 2.5f * (lw + lh) + lc + lcls;
    out[0] = loss; out[1] = lx; out[2] = ly; out[3] = lw;
    out[4] = lh;   out[5] = lc; out[6] = lcls;
}

extern "C" void kernel_launch(void* const* d_in, const int* in_sizes, int n_in,
                              void* d_out, int out_size) {
    const float* inp = (const float*)d_in[0];
    const float* tgt = (const float*)d_in[1];
    if (n_in >= 2 && in_sizes[0] == B * T * 5) {  // defensive: swap if order differs
        inp = (const float*)d_in[1];
        tgt = (const float*)d_in[0];
    }
    float* out = (float*)d_out;

    k_init<<<(CNT + 1023) / 1024, 1024>>>();
    k_targets<<<1, B * T>>>(inp, tgt);
    k_conf<<<(CNT + 255) / 256, 256>>>(inp);
    k_final<<<1, 1>>>(out);
}

// round 2
// speedup vs baseline: 1.5284x; 1.5284x over previous
#include <cuda_runtime.h>

#define B 16
#define A 3
#define C 80
#define H 76
#define W 76
#define T 50
#define HW (H*W)                 // 5776
#define CNT (B*A*H*W)            // 277248
#define CNT4 (CNT/4)             // 69312 float4 elements in conf planes
#define CH (5+C)                 // 85
#define INCH (A*CH)              // 255
#define NTHREADS 256
#define NB_CONF ((CNT4 + NTHREADS - 1) / NTHREADS)   // 271
#define NB_TOTAL (NB_CONF + B)                        // 287
#define MAXHITS (B*T*A)                               // 2400

// Accumulator slots:
// 0 sx, 1 sy, 2 sw, 3 sh, 4 sconf_obj, 5 scls, 6 n_m,
// 7 dense_conf_sum (all cells), 8 sub_conf_sum (hit cells), 9 n_hit
__device__ float        g_acc[10];
__device__ unsigned int g_done;
__device__ int          g_nhits;
__device__ int          g_hits[MAXHITS];
__device__ int          g_objhit[CNT];     // zero-init at load; kernel self-cleans

__device__ __forceinline__ float sigm(float z) { return 1.f / (1.f + expf(-z)); }

// bce against target 0: -clip(log(1-p), -100)
__device__ __forceinline__ float bce0(float z) {
    float s = sigm(z);
    return -fmaxf(logf(1.f - s), -100.f);
}
// full bce, mirrors reference clip semantics
__device__ __forceinline__ float bce_f(float p, float t) {
    float lp = fmaxf(logf(p), -100.f);
    float lq = fmaxf(logf(1.f - p), -100.f);
    return -(t * lp + (1.f - t) * lq);
}

__global__ void __launch_bounds__(NTHREADS)
yolo_loss_all(const float* __restrict__ inp, const float* __restrict__ tgt,
              float* __restrict__ out) {
    const int tid = threadIdx.x;
    const int bid = blockIdx.x;

    __shared__ int   s_cell[T];
    __shared__ int   s_cls[T];
    __shared__ float s_tx[T], s_ty[T], s_tw[T], s_th[T];
    __shared__ float red[10][8];
    __shared__ unsigned int s_last;

    float vals[10];
    #pragma unroll
    for (int j = 0; j < 10; j++) vals[j] = 0.f;

    if (bid < NB_CONF) {
        // ---- dense conf pass over all B*A*H*W cells (float4 over 48 planes) ----
        int v = bid * NTHREADS + tid;
        if (v < CNT4) {
            int plane = v / (HW / 4);          // 0..47  (HW/4 = 1444)
            int j     = v - plane * (HW / 4);
            int b = plane / A, a = plane - b * A;
            const float4* src =
                (const float4*)(inp + (size_t)(b * INCH + a * CH + 4) * HW);
            float4 q = src[j];
            vals[7] = bce0(q.x) + bce0(q.y) + bce0(q.z) + bce0(q.w);
        }
    } else {
        // ---- per-batch target building: one block per batch ----
        const int b = bid - NB_CONF;
        const float aw[3] = {1.25f, 2.0f, 4.125f};   // ANCHORS / (608/76)
        const float ah[3] = {1.625f, 3.75f, 2.875f};

        if (tid < T) {
            const float* tp = tgt + (size_t)(b * T + tid) * 5;
            float c0 = tp[0], c1 = tp[1], c2 = tp[2], c3 = tp[3], c4 = tp[4];
            bool valid = (c0 + c1 + c2 + c3 + c4) != 0.f;
            int cls = (int)c0;
            float gx = c1 * (float)W, gy = c2 * (float)H;
            float gw = c3 * (float)W, gh = c4 * (float)H;
            int gi = (int)gx, gj = (int)gy;
            bool ok = valid && (gj < H) && (gi < W);

            float a1 = (gw + 1.f) * (gh + 1.f);
            float bestv = -1.f; int best = 0;
            #pragma unroll
            for (int a = 0; a < A; a++) {
                float inter = fmaxf(fminf(gw, aw[a]) + 1.f, 0.f) *
                              fmaxf(fminf(gh, ah[a]) + 1.f, 0.f);
                float a2 = (aw[a] + 1.f) * (ah[a] + 1.f);
                float iou = inter / (a1 + a2 - inter + 1e-16f);
                if (iou > bestv) { bestv = iou; best = a; }
                if (valid && iou > 0.5f && gj >= 0 && gj < H && gi >= 0 && gi < W) {
                    int idx = ((b * A + a) * H + gj) * W + gi;
                    int old = atomicExch(&g_objhit[idx], 1);
                    if (old == 0) {
                        int slot = atomicAdd(&g_nhits, 1);
                        g_hits[slot] = idx;
                        float z = inp[(size_t)(b * INCH + a * CH + 4) * HW + gj * W + gi];
                        vals[8] += bce0(z);   // subtract later
                        vals[9] += 1.f;       // hit count
                    }
                }
            }
            s_cell[tid] = ok ? ((b * A + best) * H + gj) * W + gi : -1;
            s_cls[tid]  = cls;
            s_tx[tid]   = gx - (float)gi;
            s_ty[tid]   = gy - (float)gj;
            s_tw[tid]   = logf(gw / aw[best] + 1e-16f);
            s_th[tid]   = logf(gh / ah[best] + 1e-16f);
        }
        __syncthreads();

        if (tid < T) {
            int cell = s_cell[tid];
            if (cell >= 0) {
                // winner: last target (largest index) hitting this cell
                // tcls: multi-hot over all targets hitting the cell
                unsigned cm0 = 0, cm1 = 0, cm2 = 0;
                bool win = true;
                #pragma unroll 2
                for (int u = 0; u < T; u++) {
                    if (s_cell[u] == cell) {
                        if (u > tid) win = false;
                        int cc = s_cls[u];
                        if (cc < 32)      cm0 |= 1u << cc;
                        else if (cc < 64) cm1 |= 1u << (cc - 32);
                        else              cm2 |= 1u << (cc - 64);
                    }
                }
                if (win) {
                    int plane = cell / HW;            // b*A + best
                    int best  = plane - b * A;
                    int rem   = cell - plane * HW;    // gj*W + gi
                    const float* p =
                        inp + (size_t)(b * INCH + best * CH) * HW + rem;

                    vals[0] = bce_f(sigm(p[0]),      s_tx[tid]);
                    vals[1] = bce_f(sigm(p[HW]),     s_ty[tid]);
                    float dw = p[2 * HW] - s_tw[tid]; vals[2] = dw * dw;
                    float dh = p[3 * HW] - s_th[tid]; vals[3] = dh * dh;
                    vals[4] = -fmaxf(logf(sigm(p[4 * HW])), -100.f); // bce(conf,1)
                    float scls = 0.f;
                    #pragma unroll 8
                    for (int c = 0; c < C; c++) {
                        unsigned bit = (c < 32) ? (cm0 >> c)
                                     : (c < 64) ? (cm1 >> (c - 32))
                                                : (cm2 >> (c - 64));
                        float t = (bit & 1u) ? 1.f : 0.f;
                        scls += bce_f(sigm(p[(size_t)(5 + c) * HW]), t);
                    }
                    vals[5] = scls;
                    vals[6] = 1.f;
                }
            }
        }
    }

    // ---- block reduction of the 10 accumulators, one atomicAdd each ----
    const int wid = tid >> 5, lid = tid & 31;
    #pragma unroll
    for (int j = 0; j < 10; j++) {
        float v = vals[j];
        #pragma unroll
        for (int o = 16; o > 0; o >>= 1) v += __shfl_down_sync(0xffffffffu, v, o);
        if (lid == 0) red[j][wid] = v;
    }
    __syncthreads();
    if (wid == 0) {
        #pragma unroll
        for (int j = 0; j < 10; j++) {
            float v = (lid < (NTHREADS >> 5)) ? red[j][lid] : 0.f;
            #pragma unroll
            for (int o = 4; o > 0; o >>= 1) v += __shfl_down_sync(0xffffffffu, v, o);
            if (lid == 0 && v != 0.f) atomicAdd(&g_acc[j], v);
        }
    }

    // ---- completion: last block finalizes + cleans persistent state ----
    __threadfence();
    __syncthreads();
    if (tid == 0) s_last = atomicAdd(&g_done, 1u);
    __syncthreads();
    if (s_last == (unsigned)(NB_TOTAL - 1)) {
        if (tid == 0) {
            volatile float* g = g_acc;
            const float inv = 1.f / (float)CNT;
            float nm   = g[6];
            float nnm  = (float)CNT - g[9];
            float lx = (g[0] * inv) / nm;
            float ly = (g[1] * inv) / nm;
            float lw = (g[2] * inv) / nm;
            float lh = (g[3] * inv) / nm;
            float lc = (g[4] * inv) / nm + 0.5f * ((g[7] - g[8]) * inv) / nnm;
            float lcls = g[5] / (nm * (float)C) / nm;
            float loss = 2.5f * (lx + ly) + 2.5f * (lw + lh) + lc + lcls;
            out[0] = loss; out[1] = lx; out[2] = ly; out[3] = lw;
            out[4] = lh;   out[5] = lc; out[6] = lcls;
        }
        __syncthreads();   // out written before state reset
        if (tid < 10) g_acc[tid] = 0.f;
        int nh = g_nhits;
        for (int i = tid; i < nh; i += NTHREADS) g_objhit[g_hits[i]] = 0;
        __syncthreads();
        if (tid == 0) { g_nhits = 0; g_done = 0u; }
    }
}

extern "C" void kernel_launch(void* const* d_in, const int* in_sizes, int n_in,
                              void* d_out, int out_size) {
    const float* inp = (const float*)d_in[0];
    const float* tgt = (const float*)d_in[1];
    if (n_in >= 2 && in_sizes[0] == B * T * 5) {   // defensive order check
        inp = (const float*)d_in[1];
        tgt = (const float*)d_in[0];
    }
    yolo_loss_all<<<NB_TOTAL, NTHREADS>>>(inp, tgt, (float*)d_out);
}

// round 3
// speedup vs baseline: 2.9175x; 1.9089x over previous
#include <cuda_runtime.h>

#define B 16
#define A 3
#define C 80
#define H 76
#define W 76
#define T 50
#define HW (H*W)                  // 5776
#define CNT (B*A*H*W)             // 277248
#define CNT4 (CNT/4)              // 69312 float4 elems across 48 conf planes
#define THIRD4 (CNT4/3)           // 23104
#define Q4 (HW/4)                 // 1444 float4 per plane
#define CH 85
#define NTHREADS 256
#define NB_CONF ((THIRD4 + NTHREADS - 1) / NTHREADS)   // 91
#define NB_TOTAL (NB_CONF + B)                          // 107
#define BMW ((A*HW + 31) / 32)                          // 542 bitmap words

// Persistent state (self-resetting): 10 accumulators + completion counter.
// 0 sx, 1 sy, 2 sw, 3 sh, 4 sconf_obj, 5 scls, 6 n_m,
// 7 dense_conf_sum, 8 sub_conf_sum (hit cells), 9 n_hit
__device__ float        g_acc[10];
__device__ unsigned int g_done;

// min(softplus(z), 100) == -clip(log(1-sigmoid(z)), -100)
__device__ __forceinline__ float sp_pos(float z) {
    float sp = fmaxf(z, 0.f) + __logf(1.f + __expf(-fabsf(z)));
    return fminf(sp, 100.f);
}
// bce(sigmoid(z), t) with reference clip semantics
__device__ __forceinline__ float bce_z(float z, float t) {
    return t * sp_pos(-z) + (1.f - t) * sp_pos(z);
}

__global__ void __launch_bounds__(NTHREADS)
yolo_loss_all(const float* __restrict__ inp, const float* __restrict__ tgt,
              float* __restrict__ out) {
    const int tid = threadIdx.x;
    const int bid = blockIdx.x;
    const int wid = tid >> 5, lid = tid & 31;

    __shared__ float red[10][8];
    __shared__ unsigned int s_last;

    float vals[10];
    #pragma unroll
    for (int j = 0; j < 10; j++) vals[j] = 0.f;

    if (bid < NB_CONF) {
        // ======== dense conf pass: 3 float4 per thread (MLP=3) ========
        int v = bid * NTHREADS + tid;
        float acc = 0.f;
        if (v < THIRD4) {
            #pragma unroll
            for (int r = 0; r < 3; r++) {
                int e = v + r * THIRD4;
                int plane = e / Q4;            // 0..47
                int j = e - plane * Q4;
                const float4* src =
                    (const float4*)(inp + (size_t)(CH * plane + 4) * HW);
                float4 q = src[j];
                acc += sp_pos(q.x) + sp_pos(q.y) + sp_pos(q.z) + sp_pos(q.w);
            }
        }
        // single-slot block reduction
        #pragma unroll
        for (int o = 16; o > 0; o >>= 1) acc += __shfl_down_sync(0xffffffffu, acc, o);
        if (lid == 0) red[0][wid] = acc;
        __syncthreads();
        if (wid == 0) {
            float vv = (lid < (NTHREADS >> 5)) ? red[0][lid] : 0.f;
            #pragma unroll
            for (int o = 4; o > 0; o >>= 1) vv += __shfl_down_sync(0xffffffffu, vv, o);
            if (lid == 0) atomicAdd(&g_acc[7], vv);
        }
    } else {
        // ======== target block: one per batch ========
        const int b = bid - NB_CONF;
        __shared__ unsigned int bm[BMW];            // per-batch hit bitmap
        __shared__ int   s_cell[T];
        __shared__ int   s_cls[T];
        __shared__ float s_tx[T], s_ty[T], s_tw[T], s_th[T];
        __shared__ int   s_nwin;
        __shared__ long long s_woff[T];
        __shared__ float w_tx[T], w_ty[T], w_tw[T], w_th[T];
        __shared__ unsigned int w_c0[T], w_c1[T], w_c2[T];

        const float aw[3] = {1.25f, 2.0f, 4.125f};   // ANCHORS / (608/76)
        const float ah[3] = {1.625f, 3.75f, 2.875f};

        for (int i = tid; i < BMW; i += NTHREADS) bm[i] = 0u;
        if (tid == 0) s_nwin = 0;
        __syncthreads();

        // ---- phase A: geometry, noobj dedup (smem bitmap), conf-subtract ----
        if (tid < T) {
            const float* tp = tgt + (size_t)(b * T + tid) * 5;
            float c0 = tp[0], c1 = tp[1], c2 = tp[2], c3 = tp[3], c4 = tp[4];
            bool valid = (c0 + c1 + c2 + c3 + c4) != 0.f;
            float gx = c1 * (float)W, gy = c2 * (float)H;
            float gw = c3 * (float)W, gh = c4 * (float)H;
            int gi = (int)gx, gj = (int)gy;
            bool ok = valid && (gj < H) && (gi < W);

            float a1 = (gw + 1.f) * (gh + 1.f);
            float bestv = -1.f; int best = 0;
            #pragma unroll
            for (int a = 0; a < A; a++) {
                float inter = fmaxf(fminf(gw, aw[a]) + 1.f, 0.f) *
                              fmaxf(fminf(gh, ah[a]) + 1.f, 0.f);
                float a2 = (aw[a] + 1.f) * (ah[a] + 1.f);
                float iou = inter / (a1 + a2 - inter + 1e-16f);
                if (iou > bestv) { bestv = iou; best = a; }
                if (valid && iou > 0.5f && gj >= 0 && gj < H && gi >= 0 && gi < W) {
                    int li = (a * H + gj) * W + gi;            // index within batch
                    unsigned old = atomicOr(&bm[li >> 5], 1u << (li & 31));
                    if (!(old & (1u << (li & 31)))) {
                        float z = inp[(size_t)(CH * (3 * b + a) + 4) * HW + gj * W + gi];
                        vals[8] += sp_pos(z);   // subtracted from dense sum later
                        vals[9] += 1.f;
                    }
                }
            }
            s_cell[tid] = ok ? ((b * A + best) * H + gj) * W + gi : -1;
            s_cls[tid]  = (int)c0;
            s_tx[tid]   = gx - (float)gi;
            s_ty[tid]   = gy - (float)gj;
            s_tw[tid]   = __logf(gw / aw[best] + 1e-16f);
            s_th[tid]   = __logf(gh / ah[best] + 1e-16f);
        }
        __syncthreads();

        // ---- winner resolution (last-target-wins) + multi-hot class masks ----
        if (tid < T) {
            int cell = s_cell[tid];
            if (cell >= 0) {
                unsigned cm0 = 0, cm1 = 0, cm2 = 0;
                bool win = true;
                for (int u = 0; u < T; u++) {
                    if (s_cell[u] == cell) {
                        if (u > tid) win = false;
                        int cc = s_cls[u];
                        if (cc < 32)      cm0 |= 1u << cc;
                        else if (cc < 64) cm1 |= 1u << (cc - 32);
                        else              cm2 |= 1u << (cc - 64);
                    }
                }
                if (win) {
                    int slot = atomicAdd(&s_nwin, 1);
                    int plane = cell / HW;                  // b*A + anchor
                    int rem   = cell - plane * HW;
                    s_woff[slot] = (long long)CH * plane * HW + rem;
                    w_tx[slot] = s_tx[tid]; w_ty[slot] = s_ty[tid];
                    w_tw[slot] = s_tw[tid]; w_th[slot] = s_th[tid];
                    w_c0[slot] = cm0; w_c1[slot] = cm1; w_c2[slot] = cm2;
                }
            }
        }
        __syncthreads();

        // ---- phase B: warp-parallel gather of 85 channels per winner cell ----
        const int nwin = s_nwin;
        float a0 = 0.f, a1 = 0.f, a2 = 0.f, a3 = 0.f, a4 = 0.f, a5 = 0.f;
        for (int wi = wid; wi < nwin; wi += (NTHREADS / 32)) {
            const float* p = inp + s_woff[wi];
            float tx = w_tx[wi], ty = w_ty[wi], tw = w_tw[wi], th = w_th[wi];
            unsigned cm0 = w_c0[wi], cm1 = w_c1[wi], cm2 = w_c2[wi];
            // all three loads issued before use: one latency wave
            float z0 = p[(size_t)lid * HW];
            float z1 = p[(size_t)(lid + 32) * HW];
            float z2 = (lid < CH - 64) ? p[(size_t)(lid + 64) * HW] : 0.f;

            // round 1: channels 0..31 (specials live here)
            if (lid == 0)      a0 += bce_z(z0, tx);
            else if (lid == 1) a1 += bce_z(z0, ty);
            else if (lid == 2) { float d = z0 - tw; a2 += d * d; }
            else if (lid == 3) { float d = z0 - th; a3 += d * d; }
            else if (lid == 4) a4 += sp_pos(-z0);             // bce(conf, 1)
            else {
                int c = lid - 5;                               // 0..26
                a5 += (cm0 >> c) & 1u ? sp_pos(-z0) : sp_pos(z0);
            }
            // round 2: channels 32..63 -> classes 27..58
            {
                int c = lid + 27;
                unsigned bit = (c < 32) ? (cm0 >> c) : (cm1 >> (c - 32));
                a5 += bit & 1u ? sp_pos(-z1) : sp_pos(z1);
            }
            // round 3: channels 64..84 -> classes 59..79 (lanes 0..20)
            if (lid < CH - 64) {
                int c = lid + 59;
                unsigned bit = (c < 64) ? (cm1 >> (c - 32)) : (cm2 >> (c - 64));
                a5 += bit & 1u ? sp_pos(-z2) : sp_pos(z2);
            }
        }
        vals[0] = a0; vals[1] = a1; vals[2] = a2;
        vals[3] = a3; vals[4] = a4; vals[5] = a5;
        if (tid == 0) vals[6] = (float)nwin;

        // ---- 10-slot block reduction, one atomic per live slot ----
        #pragma unroll
        for (int j = 0; j < 10; j++) {
            float vv = vals[j];
            #pragma unroll
            for (int o = 16; o > 0; o >>= 1) vv += __shfl_down_sync(0xffffffffu, vv, o);
            if (lid == 0) red[j][wid] = vv;
        }
        __syncthreads();
        if (wid == 0) {
            #pragma unroll
            for (int j = 0; j < 10; j++) {
                float vv = (lid < (NTHREADS >> 5)) ? red[j][lid] : 0.f;
                #pragma unroll
                for (int o = 4; o > 0; o >>= 1) vv += __shfl_down_sync(0xffffffffu, vv, o);
                if (lid == 0 && vv != 0.f) atomicAdd(&g_acc[j], vv);
            }
        }
    }

    // ======== completion: last block finalizes + resets state ========
    __threadfence();
    __syncthreads();
    if (tid == 0) s_last = atomicAdd(&g_done, 1u);
    __syncthreads();
    if (s_last == (unsigned)(NB_TOTAL - 1)) {
        if (tid == 0) {
            volatile float* g = g_acc;
            const float inv = 1.f / (float)CNT;
            float nm  = g[6];
            float nnm = (float)CNT - g[9];
            float lx = (g[0] * inv) / nm;
            float ly = (g[1] * inv) / nm;
            float lw = (g[2] * inv) / nm;
            float lh = (g[3] * inv) / nm;
            float lc = (g[4] * inv) / nm + 0.5f * ((g[7] - g[8]) * inv) / nnm;
            float lcls = g[5] / (nm * (float)C) / nm;
            float loss = 2.5f * (lx + ly) + 2.5f * (lw + lh) + lc + lcls;
            out[0] = loss; out[1] = lx; out[2] = ly; out[3] = lw;
            out[4] = lh;   out[5] = lc; out[6] = lcls;
        }
        __syncthreads();          // out written before reset
        if (tid < 10) g_acc[tid] = 0.f;
        __syncthreads();
        if (tid == 0) g_done = 0u;
    }
}

extern "C" void kernel_launch(void* const* d_in, const int* in_sizes, int n_in,
                              void* d_out, int out_size) {
    const float* inp = (const float*)d_in[0];
    const float* tgt = (const float*)d_in[1];
    if (n_in >= 2 && in_sizes[0] == B * T * 5) {   // defensive order check
        inp = (const float*)d_in[1];
        tgt = (const float*)d_in[0];
    }
    yolo_loss_all<<<NB_TOTAL, NTHREADS>>>(inp, tgt, (float*)d_out);
}